// round 16
// baseline (speedup 1.0000x reference)
#include <cuda_runtime.h>
#include <cuda_fp16.h>
#include <cstdint>
#include <math.h>

#define B_   16384
#define S_   6
#define D_   991
#define KD   992          // half out-row stride for g_out
#define KH   1024         // padded K for half GEMM operands
#define NP   3072         // packed/padded N (stride for xg, WihP rows)
#define NPR  2976         // real packed rows (992 d x 3 gates)
#define TM   128
#define TN   128          // GEMM1 tile N
#define NT_  (NP / TN)    // 24 n-tiles (GEMM1)
#define TNR  96           // recurrent tile N (32 d's x 3 gates)
#define NTR  (NPR / TNR)  // 31 n-tiles (recurrent)
#define KCH  64           // K halfs per chunk (128 bytes/row)
#define NCHh (KH / KCH)   // 16 chunks
#define STB  ((TM + TN) * 128)        // 32768
#define SMEMB (3 * STB)               // 98304 (GEMM1)
#define STBR ((TM + TNR) * 128)       // 28672
#define SMEMR (3 * STBR)              // 86016 (recurrent)

// ------------------- scratch (device globals) ------------------------------
__device__ __half g_x   [(size_t)B_ * S_ * KH];
__device__ __half g_xg  [(size_t)S_ * B_ * NP];   // packed-96 gate layout
__device__ __half g_hA  [(size_t)B_ * KH];        // hidden ping
__device__ __half g_hB  [(size_t)B_ * KH];        // hidden pong
__device__ __half g_out [(size_t)B_ * KD];        // final hidden (fp16)
__device__ __half g_WihP[(size_t)NP * KH];        // packed, rows 2976.. zero
__device__ __half g_WhhP[(size_t)NP * KH];
__device__ float  g_bihP[NP];                     // packed bias for GEMM1
__device__ float  g_bhh [3 * KH];                 // gate-major (d stride 1024)
__device__ float  g_psum[32 * KD];
__device__ float  g_psq [32 * KD];
__device__ float  g_weff[2 * D_];
__device__ float  g_wbn [2 * KD];                 // [991],[KD+991] stay zero
__device__ float  g_shift[KD];
__device__ float  g_bbn [2];
// ragged-batch bookkeeping (permuted row space, sorted by descending seq_len)
__device__ int    g_idx[B_];
__device__ int    g_sln[B_];
__device__ int    g_cnt[8];

// --------------------------- helpers ---------------------------------------
__device__ __forceinline__ uint32_t smem_u32(const void* p) {
    uint32_t a;
    asm("{ .reg .u64 t; cvta.to.shared.u64 t, %1; cvt.u32.u64 %0, t; }" : "=r"(a) : "l"(p));
    return a;
}
__device__ __forceinline__ void cp_async16(uint32_t dst, const void* src) {
    asm volatile("cp.async.cg.shared.global [%0], [%1], 16;" :: "r"(dst), "l"(src) : "memory");
}
#define CP_COMMIT() asm volatile("cp.async.commit_group;" ::: "memory")
#define CP_WAIT(n)  asm volatile("cp.async.wait_group %0;" :: "n"(n) : "memory")

__device__ __forceinline__ void ldm4(uint32_t* r, uint32_t addr) {
    asm volatile("ldmatrix.sync.aligned.m8n8.x4.shared.b16 {%0,%1,%2,%3}, [%4];"
                 : "=r"(r[0]), "=r"(r[1]), "=r"(r[2]), "=r"(r[3]) : "r"(addr));
}
__device__ __forceinline__ void mma_h(float* c, const uint32_t* a, const uint32_t* b) {
    asm volatile(
        "mma.sync.aligned.m16n8k16.row.col.f32.f16.f16.f32 "
        "{%0,%1,%2,%3}, {%4,%5,%6,%7}, {%8,%9}, {%0,%1,%2,%3};"
        : "+f"(c[0]), "+f"(c[1]), "+f"(c[2]), "+f"(c[3])
        : "r"(a[0]), "r"(a[1]), "r"(a[2]), "r"(a[3]), "r"(b[0]), "r"(b[1]));
}
__device__ __forceinline__ float fsigmoid(float x) {
    return 1.f / (1.f + __expf(-x));
}
__device__ __forceinline__ float ftanh(float x) {
    float e = __expf(2.f * x);
    return 1.f - __fdividef(2.f, e + 1.f);
}

__device__ __forceinline__ float2 block_reduce2(float a, float b) {
    __shared__ float wa[8], wb[8];
    __shared__ float ra, rb;
    int lane = threadIdx.x & 31, w = threadIdx.x >> 5;
#pragma unroll
    for (int o = 16; o; o >>= 1) {
        a += __shfl_down_sync(0xffffffffu, a, o);
        b += __shfl_down_sync(0xffffffffu, b, o);
    }
    if (!lane) { wa[w] = a; wb[w] = b; }
    __syncthreads();
    if (threadIdx.x < 8) { a = wa[threadIdx.x]; b = wb[threadIdx.x]; }
    else { a = 0.f; b = 0.f; }
    if (w == 0) {
#pragma unroll
        for (int o = 4; o; o >>= 1) {
            a += __shfl_down_sync(0xffffffffu, a, o);
            b += __shfl_down_sync(0xffffffffu, b, o);
        }
    }
    if (threadIdx.x == 0) { ra = a; rb = b; }
    __syncthreads();
    return make_float2(ra, rb);
}

// --------------------------- deterministic counting sort --------------------
__global__ void __launch_bounds__(1024)
sort_kernel(const int* __restrict__ seq_len) {
    __shared__ int cnts[1024][6];
    __shared__ int tot[6], base[6];
    const int tid = threadIdx.x;
    const int b0 = tid * 16;
    int lc[6] = {0, 0, 0, 0, 0, 0};
#pragma unroll
    for (int k = 0; k < 16; ++k) {
        int v = seq_len[b0 + k] - 1;
        lc[v]++;
    }
#pragma unroll
    for (int v = 0; v < 6; ++v) cnts[tid][v] = lc[v];
    __syncthreads();
    if (tid < 6) {
        int run = 0;
        for (int i = 0; i < 1024; ++i) {
            int c = cnts[i][tid];
            cnts[i][tid] = run;
            run += c;
        }
        tot[tid] = run;
    }
    __syncthreads();
    if (tid == 0) {
        int acc = 0;
        for (int v = 5; v >= 0; --v) { base[v] = acc; acc += tot[v]; }
        for (int s = 0; s < 6; ++s) {
            int c = 0;
            for (int v = s; v < 6; ++v) c += tot[v];
            g_cnt[s] = c;
        }
    }
    __syncthreads();
    int off[6];
#pragma unroll
    for (int v = 0; v < 6; ++v) off[v] = base[v] + cnts[tid][v];
#pragma unroll
    for (int k = 0; k < 16; ++k) {
        int b = b0 + k;
        int v = seq_len[b] - 1;
        int p = off[v]++;
        g_idx[p] = b;
        g_sln[p] = v + 1;
    }
}

// --------------------------- weight packing --------------------------------
// Packed row rp (0..3071): nt=rp/96, cc=rp%96, grp=cc>>3, gate=grp%3,
// d = nt*32 + (grp/3)*8 + (cc&7). rows >= 2976 or d >= 991 -> zero.
__global__ void pack_weights(const float* __restrict__ Wih, const float* __restrict__ Whh,
                             const float* __restrict__ bih, const float* __restrict__ bhh) {
    size_t i = (size_t)blockIdx.x * 256 + threadIdx.x;
    if (i >= (size_t)NP * KH) return;
    int rp = (int)(i / KH), c = (int)(i - (size_t)rp * KH);
    int nt = rp / 96, cc = rp - nt * 96;
    int grp = cc >> 3, gate = grp % 3;
    int d = nt * 32 + (grp / 3) * 8 + (cc & 7);
    bool valid = (rp < NPR) && (d < D_);
    float vi = 0.f, vh = 0.f;
    if (valid && c < D_) {
        size_t src = (size_t)(gate * D_ + d) * D_ + c;
        vi = Wih[src];
        vh = Whh[src];
    }
    g_WihP[i] = __float2half_rn(vi);
    g_WhhP[i] = __float2half_rn(vh);
    if (c == 0) {
        g_bihP[rp] = valid ? bih[gate * D_ + d] : 0.f;
        if (rp < NPR)
            g_bhh[gate * KH + d] = (d < D_) ? bhh[gate * D_ + d] : 0.f;
    }
}

// --------------------------- embed + layernorm (warp per row) --------------
__global__ void __launch_bounds__(256)
embed_ln(const int* __restrict__ ns, const int* __restrict__ fs,
         const int* __restrict__ nfs, const int* __restrict__ ms,
         const float* __restrict__ ntab, const float* __restrict__ ftab,
         const float* __restrict__ nftab, const float* __restrict__ btab,
         const float* __restrict__ lng, const float* __restrict__ lnb) {
    const int gid  = blockIdx.x * 8 + (threadIdx.x >> 5);   // row = s*B + p
    const int lane = threadIdx.x & 31;
    const int s = gid >> 14;
    const int p = gid & (B_ - 1);
    if (p >= g_cnt[s]) return;
    const int b = g_idx[p];
    const int q = b * S_ + s;
    const int ni = ns[q], fi = fs[q], nfi = nfs[q], mi = ms[q];
    const float* nrow  = ntab  + (size_t)ni  * 128;
    const float* frow  = ftab  + (size_t)fi  * 84;
    const float* nfrow = nftab + (size_t)nfi * 11;
    const float* brow  = btab  + (size_t)mi  * 768;

    float arr[31];
    float s1 = 0.f, s2 = 0.f;
#pragma unroll
    for (int k = 0; k < 31; ++k) {
        int d = lane + 32 * k;
        float v = 0.f;
        if (d < D_) {
            if (d < 128)      v = nrow[d];
            else if (d < 212) v = frow[d - 128];
            else if (d < 223) v = nfrow[d - 212];
            else              v = brow[d - 223];
        }
        arr[k] = v;
        s1 += v; s2 += v * v;
    }
#pragma unroll
    for (int o = 16; o; o >>= 1) {
        s1 += __shfl_xor_sync(0xffffffffu, s1, o);
        s2 += __shfl_xor_sync(0xffffffffu, s2, o);
    }
    const float mu  = s1 * (1.f / 991.f);
    const float var = fmaxf(s2 * (1.f / 991.f) - mu * mu, 0.f);
    const float rs  = rsqrtf(var + 1e-5f);
    __half* xr = g_x + (size_t)gid * KH;
#pragma unroll
    for (int k = 0; k < 32; ++k) {
        int d = lane + 32 * k;
        float v = 0.f;
        if (k < 31 && d < D_) v = (arr[k] - mu) * rs * lng[d] + lnb[d];
        xr[d] = __float2half_rn(v);
    }
}

// --------------------------- GEMM1: xg = x @ WihP^T + bihP -----------------
// 128x128 tile, 8 warps (4m x 2n), 2 CTA/SM, 3-stage, single sync/chunk.
// Last K chunk runs only ks=0,1 (cols 992..1023 are all-zero: exact skip).
__global__ void __launch_bounds__(256, 2)
gemm_h(const __half* __restrict__ A, const __half* __restrict__ Bw,
       __half* __restrict__ C, const float* __restrict__ bias) {
    const int mt = blockIdx.x / NT_, nt = blockIdx.x % NT_;
    {
        int mtl = mt & 127;
        int cnt = g_cnt[mt >> 7];
        if (mtl * TM >= cnt) return;
    }
    extern __shared__ char sm[];
    const uint32_t sb0 = smem_u32(sm);
    const int tid = threadIdx.x;

    const __half* Ab = A  + (size_t)mt * TM * KH;
    const __half* Bb = Bw + (size_t)nt * TN * KH;

    const int row0 = tid >> 3;
    const int cg   = tid & 7;
    const uint32_t rowOff0 = (uint32_t)row0 * KH + (uint32_t)cg * 8;
    const uint32_t dst0    = (uint32_t)row0 * 128 + (uint32_t)((cg ^ (row0 & 7)) << 4);

#define PREF(stagebase, k0_) do {                                            \
    _Pragma("unroll")                                                        \
    for (int t_ = 0; t_ < 4; ++t_) {                                         \
        cp_async16((stagebase) + dst0 + t_ * 4096,                           \
                   Ab + rowOff0 + (uint32_t)t_ * 32 * KH + (k0_));           \
        cp_async16((stagebase) + (TM * 128) + dst0 + t_ * 4096,              \
                   Bb + rowOff0 + (uint32_t)t_ * 32 * KH + (k0_));           \
    }                                                                        \
    CP_COMMIT();                                                             \
} while (0)

    const int lane = tid & 31, warp = tid >> 5;
    const int mw = (warp >> 1) * 32;
    const int nw = (warp & 1) * 64;
    const int g  = lane >> 2, q = lane & 3;

    uint32_t aRB[2];
#pragma unroll
    for (int i = 0; i < 2; ++i) aRB[i] = (uint32_t)(mw + i * 16 + (lane & 15)) * 128;
    const uint32_t aSw = (uint32_t)((mw + (lane & 15)) & 7);
    const uint32_t aPar = (uint32_t)(lane >> 4);
    uint32_t bRB[4], bSw[4];
#pragma unroll
    for (int jp = 0; jp < 4; ++jp) {
        uint32_t br = (uint32_t)(nw + jp * 16 + (lane & 7) + ((lane >> 4) << 3));
        bRB[jp] = br * 128;
        bSw[jp] = br & 7;
    }
    const uint32_t bPar = (uint32_t)((lane >> 3) & 1);

    float acc[2][8][4];
#pragma unroll
    for (int i = 0; i < 2; i++)
#pragma unroll
        for (int j = 0; j < 8; j++)
#pragma unroll
            for (int e = 0; e < 4; e++) acc[i][j][e] = 0.f;

    PREF(sb0, 0);
    PREF(sb0 + STB, KCH);

#pragma unroll 1
    for (int c = 0; c < NCHh; ++c) {
        if (c + 1 < NCHh) CP_WAIT(1);
        else              CP_WAIT(0);
        __syncthreads();
        if (c + 2 < NCHh) PREF(sb0 + ((c + 2) % 3) * STB, (uint32_t)(c + 2) * KCH);

        const int nks = (c == NCHh - 1) ? 2 : 4;   // tail: cols >= 992 are zero
        const uint32_t sA  = sb0 + (c % 3) * STB;
        const uint32_t sBq = sA + TM * 128;
        uint32_t a0[4], a1[4];
        {
            uint32_t kg = aPar;
            ldm4(a0, sA + aRB[0] + ((kg ^ aSw) << 4));
            ldm4(a1, sA + aRB[1] + ((kg ^ aSw) << 4));
        }
#pragma unroll
        for (int ks = 0; ks < 4; ++ks) {
            if (ks >= nks) break;
            uint32_t an0[4], an1[4];
            const bool more = (ks + 1 < nks);
            if (more) {
                uint32_t kg = 2 * (ks + 1) + aPar;
                ldm4(an0, sA + aRB[0] + ((kg ^ aSw) << 4));
                ldm4(an1, sA + aRB[1] + ((kg ^ aSw) << 4));
            }
#pragma unroll
            for (int jp = 0; jp < 4; ++jp) {
                uint32_t bf[4];
                uint32_t kg = 2 * ks + bPar;
                ldm4(bf, sBq + bRB[jp] + ((kg ^ bSw[jp]) << 4));
                mma_h(acc[0][2 * jp],     a0, bf);
                mma_h(acc[0][2 * jp + 1], a0, bf + 2);
                mma_h(acc[1][2 * jp],     a1, bf);
                mma_h(acc[1][2 * jp + 1], a1, bf + 2);
            }
            if (more) {
#pragma unroll
                for (int e = 0; e < 4; ++e) { a0[e] = an0[e]; a1[e] = an1[e]; }
            }
        }
    }
#undef PREF

    const long m0 = (long)mt * TM;
    const int  n0 = nt * TN;
#pragma unroll
    for (int i = 0; i < 2; ++i) {
        const long r0 = m0 + mw + i * 16 + g;
#pragma unroll
        for (int j = 0; j < 8; ++j) {
            const int colg = n0 + nw + j * 8 + 2 * q;
            const float2 bb = *(const float2*)(bias + colg);
            *(__half2*)(C + r0 * NP + colg) =
                __floats2half2_rn(acc[i][j][0] + bb.x, acc[i][j][1] + bb.y);
            *(__half2*)(C + (r0 + 8) * NP + colg) =
                __floats2half2_rn(acc[i][j][2] + bb.x, acc[i][j][3] + bb.y);
        }
    }
}

// --------------------------- recurrent GEMM + fused GRU --------------------
// gh = h_in @ WhhP^T; epilogue applies GRU gates, writes h_out (ping-pong).
// Tile 128x96, 8 warps (4m x 2n), warp tile 32x48. Tail chunk: ks=0,1 only.
__global__ void __launch_bounds__(256, 2)
gemm_rec(const __half* __restrict__ Hin, __half* __restrict__ Hout, int step) {
    const int mt = blockIdx.x / NTR, nt = blockIdx.x % NTR;
    if (mt * TM >= g_cnt[step]) return;
    extern __shared__ char sm[];
    const uint32_t sb0 = smem_u32(sm);
    const int tid = threadIdx.x;

    const __half* Ab = Hin    + (size_t)mt * TM * KH;
    const __half* Bb = g_WhhP + (size_t)nt * TNR * KH;

    const int row0 = tid >> 3;
    const int cg   = tid & 7;
    const uint32_t rowOff0 = (uint32_t)row0 * KH + (uint32_t)cg * 8;
    const uint32_t dst0    = (uint32_t)row0 * 128 + (uint32_t)((cg ^ (row0 & 7)) << 4);

#define PREFR(stagebase, k0_) do {                                           \
    _Pragma("unroll")                                                        \
    for (int t_ = 0; t_ < 4; ++t_)                                           \
        cp_async16((stagebase) + dst0 + t_ * 4096,                           \
                   Ab + rowOff0 + (uint32_t)t_ * 32 * KH + (k0_));           \
    _Pragma("unroll")                                                        \
    for (int t_ = 0; t_ < 3; ++t_)                                           \
        cp_async16((stagebase) + (TM * 128) + dst0 + t_ * 4096,              \
                   Bb + rowOff0 + (uint32_t)t_ * 32 * KH + (k0_));           \
    CP_COMMIT();                                                             \
} while (0)

    const int lane = tid & 31, warp = tid >> 5;
    const int mw = (warp >> 1) * 32;    // 4 m-warps
    const int nw = (warp & 1) * 48;     // 2 n-warps
    const int g  = lane >> 2, q = lane & 3;

    uint32_t aRB[2];
#pragma unroll
    for (int i = 0; i < 2; ++i) aRB[i] = (uint32_t)(mw + i * 16 + (lane & 15)) * 128;
    const uint32_t aSw = (uint32_t)((mw + (lane & 15)) & 7);
    const uint32_t aPar = (uint32_t)(lane >> 4);
    uint32_t bRB[3], bSw[3];
#pragma unroll
    for (int jp = 0; jp < 3; ++jp) {
        uint32_t br = (uint32_t)(nw + jp * 16 + (lane & 7) + ((lane >> 4) << 3));
        bRB[jp] = br * 128;
        bSw[jp] = br & 7;
    }
    const uint32_t bPar = (uint32_t)((lane >> 3) & 1);

    float acc[2][6][4];
#pragma unroll
    for (int i = 0; i < 2; i++)
#pragma unroll
        for (int j = 0; j < 6; j++)
#pragma unroll
            for (int e = 0; e < 4; e++) acc[i][j][e] = 0.f;

    PREFR(sb0, 0);
    PREFR(sb0 + STBR, KCH);

#pragma unroll 1
    for (int c = 0; c < NCHh; ++c) {
        if (c + 1 < NCHh) CP_WAIT(1);
        else              CP_WAIT(0);
        __syncthreads();
        if (c + 2 < NCHh) PREFR(sb0 + ((c + 2) % 3) * STBR, (uint32_t)(c + 2) * KCH);

        const int nks = (c == NCHh - 1) ? 2 : 4;   // tail: cols >= 992 are zero
        const uint32_t sA  = sb0 + (c % 3) * STBR;
        const uint32_t sBq = sA + TM * 128;
        uint32_t a0[4], a1[4];
        {
            uint32_t kg = aPar;
            ldm4(a0, sA + aRB[0] + ((kg ^ aSw) << 4));
            ldm4(a1, sA + aRB[1] + ((kg ^ aSw) << 4));
        }
#pragma unroll
        for (int ks = 0; ks < 4; ++ks) {
            if (ks >= nks) break;
            uint32_t an0[4], an1[4];
            const bool more = (ks + 1 < nks);
            if (more) {
                uint32_t kg = 2 * (ks + 1) + aPar;
                ldm4(an0, sA + aRB[0] + ((kg ^ aSw) << 4));
                ldm4(an1, sA + aRB[1] + ((kg ^ aSw) << 4));
            }
#pragma unroll
            for (int jp = 0; jp < 3; ++jp) {
                uint32_t bf[4];
                uint32_t kg = 2 * ks + bPar;
                ldm4(bf, sBq + bRB[jp] + ((kg ^ bSw[jp]) << 4));
                mma_h(acc[0][2 * jp],     a0, bf);
                mma_h(acc[0][2 * jp + 1], a0, bf + 2);
                mma_h(acc[1][2 * jp],     a1, bf);
                mma_h(acc[1][2 * jp + 1], a1, bf + 2);
            }
            if (more) {
#pragma unroll
                for (int e = 0; e < 4; ++e) { a0[e] = an0[e]; a1[e] = an1[e]; }
            }
        }
    }
#undef PREFR

    // fused GRU epilogue. acc[i][j]: gate = j%3, d-block b = j/3.
    const long m0 = (long)mt * TM;
    const int  w1 = warp & 1;
    const __half* xgbase = g_xg + (size_t)step * B_ * NP;
#pragma unroll
    for (int i = 0; i < 2; ++i) {
        const long R = m0 + mw + i * 16 + g;
        const int sl0 = g_sln[R], sl1 = g_sln[R + 8];
#pragma unroll
        for (int b = 0; b < 2; ++b) {
            const int D   = nt * 32 + (w1 * 2 + b) * 8 + 2 * q;
            const int rpb = nt * 96 + (w1 * 2 + b) * 24 + 2 * q;
            const float2 br_ = *(const float2*)(g_bhh + D);
            const float2 bz_ = *(const float2*)(g_bhh + KH + D);
            const float2 bn_ = *(const float2*)(g_bhh + 2 * KH + D);
#pragma unroll
            for (int half_ = 0; half_ < 2; ++half_) {
                const long row = R + half_ * 8;
                const int  sl  = half_ ? sl1 : sl0;
                const int  eo  = half_ * 2;
                const __half2* xgr = (const __half2*)(xgbase + row * NP);
                float2 xr = __half22float2(xgr[(rpb >> 1)]);
                float2 xz = __half22float2(xgr[(rpb >> 1) + 4]);
                float2 xn = __half22float2(xgr[(rpb >> 1) + 8]);
                float2 hp = __half22float2(*(const __half2*)(Hin + row * KH + D));
                float r0 = fsigmoid(xr.x + acc[i][3 * b + 0][eo]     + br_.x);
                float r1 = fsigmoid(xr.y + acc[i][3 * b + 0][eo + 1] + br_.y);
                float z0 = fsigmoid(xz.x + acc[i][3 * b + 1][eo]     + bz_.x);
                float z1 = fsigmoid(xz.y + acc[i][3 * b + 1][eo + 1] + bz_.y);
                float n0 = ftanh(xn.x + r0 * (acc[i][3 * b + 2][eo]     + bn_.x));
                float n1 = ftanh(xn.y + r1 * (acc[i][3 * b + 2][eo + 1] + bn_.y));
                float h0 = (1.f - z0) * n0 + z0 * hp.x;
                float h1 = (1.f - z1) * n1 + z1 * hp.y;
                __half2 hh = __floats2half2_rn(h0, h1);
                *(__half2*)(Hout + row * KH + D) = hh;
                if (sl - 1 == step)
                    *(__half2*)(g_out + row * KD + D) = hh;
            }
        }
    }
}

// --------------------------- GRU t=0 (h0=0, gh=b_hh; packed xg) ------------
__global__ void __launch_bounds__(1024)
gru0() {
    unsigned i = blockIdx.x * 1024u + threadIdx.x;
    if (i >= (unsigned)(B_ * 496)) return;
    int p = i / 496;
    int j = i - p * 496;
    const int d  = 2 * j;                 // 0..990
    const int rp = (d >> 5) * 96 + ((d & 31) >> 3) * 24 + (d & 7);
    const __half2* xg = (const __half2*)(g_xg + (size_t)p * NP);
    float2 xr = __half22float2(xg[(rp >> 1)]);
    float2 xz = __half22float2(xg[(rp >> 1) + 4]);
    float2 xn = __half22float2(xg[(rp >> 1) + 8]);
    float2 hr = *(const float2*)(g_bhh + d);
    float2 hz = *(const float2*)(g_bhh + KH + d);
    float2 hn = *(const float2*)(g_bhh + 2 * KH + d);
    float r0 = fsigmoid(xr.x + hr.x);
    float r1 = fsigmoid(xr.y + hr.y);
    float z0 = fsigmoid(xz.x + hz.x);
    float z1 = fsigmoid(xz.y + hz.y);
    float n0 = ftanh(xn.x + r0 * hn.x);
    float n1 = ftanh(xn.y + r1 * hn.y);
    float h0 = (1.f - z0) * n0;
    float h1 = (1.f - z1) * n1;
    __half2 hh = __floats2half2_rn(h0, h1);
    *(__half2*)(g_hA + (size_t)p * KH + d) = hh;
    if (g_sln[p] == 1)
        *(__half2*)(g_out + (size_t)p * KD + d) = hh;
}

// --------------------------- batchnorm + folded head -----------------------
// g_out is half; process half2 columns (496 per row).
__global__ void bn_partial() {
    __shared__ float ssx[8][33], sqx[8][33], ssy[8][33], sqy[8][33];
    int col2 = blockIdx.x * 32 + threadIdx.x;   // 0..495 (+pad)
    int ty = threadIdx.y;
    float sx = 0.f, qx = 0.f, sy = 0.f, qy = 0.f;
    if (col2 < 496) {
        for (int r = blockIdx.y * 8 + ty; r < B_; r += 256) {
            float2 v = __half22float2(((const __half2*)(g_out + (size_t)r * KD))[col2]);
            sx += v.x; qx += v.x * v.x;
            sy += v.y; qy += v.y * v.y;
        }
    }
    ssx[ty][threadIdx.x] = sx; sqx[ty][threadIdx.x] = qx;
    ssy[ty][threadIdx.x] = sy; sqy[ty][threadIdx.x] = qy;
    __syncthreads();
    if (ty == 0 && col2 < 496) {
        float Sx = 0.f, Qx = 0.f, Sy = 0.f, Qy = 0.f;
#pragma unroll
        for (int k = 0; k < 8; k++) {
            Sx += ssx[k][threadIdx.x]; Qx += sqx[k][threadIdx.x];
            Sy += ssy[k][threadIdx.x]; Qy += sqy[k][threadIdx.x];
        }
        g_psum[blockIdx.y * KD + 2 * col2]     = Sx;
        g_psq [blockIdx.y * KD + 2 * col2]     = Qx;
        g_psum[blockIdx.y * KD + 2 * col2 + 1] = Sy;
        g_psq [blockIdx.y * KD + 2 * col2 + 1] = Qy;
    }
}

__global__ void weff_kernel(const float* __restrict__ W2, const float* __restrict__ W1) {
    int gw   = blockIdx.x * 8 + (threadIdx.x >> 5);
    int lane = threadIdx.x & 31;
    if (gw >= 2 * D_) return;
    int o = gw / D_, d = gw - o * D_;
    float acc = 0.f;
    for (int j = lane; j < 2 * D_; j += 32)
        acc += W2[o * (2 * D_) + j] * W1[(size_t)j * D_ + d];
#pragma unroll
    for (int off = 16; off; off >>= 1) acc += __shfl_down_sync(0xffffffffu, acc, off);
    if (lane == 0) g_weff[gw] = acc;
}

__global__ void bn_finalize(const float* __restrict__ bn_g, const float* __restrict__ bn_b) {
    int d = blockIdx.x * 256 + threadIdx.x;
    if (d >= D_) return;
    float s = 0.f, q = 0.f;
#pragma unroll
    for (int p = 0; p < 32; p++) { s += g_psum[p * KD + d]; q += g_psq[p * KD + d]; }
    float mu  = s * (1.f / 16384.f);
    float var = fmaxf(q * (1.f / 16384.f) - mu * mu, 0.f);
    float sc  = bn_g[d] * rsqrtf(var + 1e-4f);
    g_shift[d]    = bn_b[d] - mu * sc;
    g_wbn[d]      = g_weff[d]      * sc;
    g_wbn[KD + d] = g_weff[D_ + d] * sc;
}

__global__ void bbn_kernel(const float* __restrict__ W2, const float* __restrict__ b1,
                           const float* __restrict__ b2) {
    int o = blockIdx.x;
    float acc = 0.f;
    for (int j = threadIdx.x; j < 2 * D_; j += 256) acc += W2[o * (2 * D_) + j] * b1[j];
    for (int d = threadIdx.x; d < D_; d += 256)     acc += g_weff[o * D_ + d] * g_shift[d];
    float2 t = block_reduce2(acc, 0.f);
    if (threadIdx.x == 0) g_bbn[o] = t.x + b2[o];
}

__global__ void logits_kernel(float* __restrict__ out) {
    int gw   = (blockIdx.x * 256 + threadIdx.x) >> 5;
    int lane = threadIdx.x & 31;
    if (gw >= B_) return;
    const __half2* row = (const __half2*)(g_out + (size_t)gw * KD);
    float a0 = 0.f, a1 = 0.f;
    for (int d2 = lane; d2 < 496; d2 += 32) {      // col 991 pad: wbn[991]=0
        float2 v = __half22float2(row[d2]);
        const float2 w0 = *(const float2*)(g_wbn + 2 * d2);
        const float2 w1 = *(const float2*)(g_wbn + KD + 2 * d2);
        a0 += v.x * w0.x + v.y * w0.y;
        a1 += v.x * w1.x + v.y * w1.y;
    }
#pragma unroll
    for (int o = 16; o; o >>= 1) {
        a0 += __shfl_down_sync(0xffffffffu, a0, o);
        a1 += __shfl_down_sync(0xffffffffu, a1, o);
    }
    if (lane == 0) {
        int b = g_idx[gw];
        out[2 * b]     = a0 + g_bbn[0];
        out[2 * b + 1] = a1 + g_bbn[1];
    }
}

// --------------------------- launch -----------------------------------------
extern "C" void kernel_launch(void* const* d_in, const int* in_sizes, int n_in,
                              void* d_out, int out_size) {
    const int*   node_seq   = (const int*)d_in[0];
    const int*   fin_seq    = (const int*)d_in[1];
    const int*   nfin_seq   = (const int*)d_in[2];
    const int*   mda_seq    = (const int*)d_in[3];
    const int*   seq_len    = (const int*)d_in[4];
    const float* node_table = (const float*)d_in[5];
    const float* fin_table  = (const float*)d_in[6];
    const float* nfin_table = (const float*)d_in[7];
    const float* bert_table = (const float*)d_in[8];
    const float* ln_g = (const float*)d_in[9];
    const float* ln_b = (const float*)d_in[10];
    const float* W_ih = (const float*)d_in[11];
    const float* W_hh = (const float*)d_in[12];
    const float* b_ih = (const float*)d_in[13];
    const float* b_hh = (const float*)d_in[14];
    const float* bn_g = (const float*)d_in[15];
    const float* bn_b = (const float*)d_in[16];
    const float* W1   = (const float*)d_in[17];
    const float* b1   = (const float*)d_in[18];
    const float* W2   = (const float*)d_in[19];
    const float* b2   = (const float*)d_in[20];

    __half *px, *pxg, *pWihP, *phA, *phB;
    float *pbihP;
    cudaGetSymbolAddress((void**)&px,    g_x);
    cudaGetSymbolAddress((void**)&pxg,   g_xg);
    cudaGetSymbolAddress((void**)&pWihP, g_WihP);
    cudaGetSymbolAddress((void**)&pbihP, g_bihP);
    cudaGetSymbolAddress((void**)&phA,   g_hA);
    cudaGetSymbolAddress((void**)&phB,   g_hB);

    cudaFuncSetAttribute(gemm_h,   cudaFuncAttributeMaxDynamicSharedMemorySize, SMEMB);
    cudaFuncSetAttribute(gemm_rec, cudaFuncAttributeMaxDynamicSharedMemorySize, SMEMR);

    sort_kernel<<<1, 1024>>>(seq_len);
    pack_weights<<<(NP * KH + 255) / 256, 256>>>(W_ih, W_hh, b_ih, b_hh);
    embed_ln<<<B_ * S_ / 8, 256>>>(node_seq, fin_seq, nfin_seq, mda_seq,
                                   node_table, fin_table, nfin_table, bert_table,
                                   ln_g, ln_b);

    // GEMM1: xg = x @ WihP^T + bihP  (ragged: per-s active prefix)
    gemm_h<<<(B_ * S_ / TM) * NT_, 256, SMEMB>>>(px, pWihP, pxg, pbihP);

    // GRU t=0 (h0=0 => gh = b_hh) -> writes g_hA
    gru0<<<(B_ * 496 + 1023) / 1024, 1024>>>();

    // steps 1..5: recurrent GEMM with fused GRU epilogue (ping-pong h)
    __half* bufs[2] = {phA, phB};
    for (int t = 1; t < S_; ++t) {
        __half* hin  = bufs[(t + 1) & 1];
        __half* hout = bufs[t & 1];
        gemm_rec<<<(B_ / TM) * NTR, 256, SMEMR>>>(hin, hout, t);
    }

    // head constant-folding (independent; late so ncu slot catches GEMMs)
    weff_kernel<<<(2 * D_ + 7) / 8, 256>>>(W2, W1);

    // batchnorm stats + folded head
    bn_partial<<<dim3(16, 32), dim3(32, 8)>>>();
    bn_finalize<<<(D_ + 255) / 256, 256>>>(bn_g, bn_b);
    bbn_kernel<<<2, 256>>>(W2, b1, b2);
    logits_kernel<<<(B_ * 32 + 255) / 256, 256>>>((float*)d_out);
}

// round 17
// speedup vs baseline: 1.0247x; 1.0247x over previous
#include <cuda_runtime.h>
#include <cuda_fp16.h>
#include <cstdint>
#include <math.h>

#define B_   16384
#define S_   6
#define D_   991
#define KD   992          // half out-row stride for g_out
#define KH   1024         // padded K for half GEMM operands
#define NP   3072         // packed/padded N (stride for xg, WihP rows)
#define NPR  2976         // real packed rows (992 d x 3 gates)
#define TM   128
#define TN   128          // GEMM1 tile N
#define NT_  (NP / TN)    // 24 n-tiles (GEMM1)
#define TNR  96           // recurrent tile N (32 d's x 3 gates)
#define NTR  (NPR / TNR)  // 31 n-tiles (recurrent)
#define KCH  64           // K halfs per chunk (128 bytes/row)
#define NCHh (KH / KCH)   // 16 chunks
#define STB  ((TM + TN) * 128)        // 32768
#define SMEMB (3 * STB)               // 98304 (GEMM1)
#define STBR ((TM + TNR) * 128)       // 28672
#define SMEMR (3 * STBR)              // 86016 (recurrent)

// ------------------- scratch (device globals) ------------------------------
__device__ __half g_x   [(size_t)B_ * S_ * KH];
__device__ __half g_xg  [(size_t)S_ * B_ * NP];   // packed-96 gate layout
__device__ __half g_hA  [(size_t)B_ * KH];        // hidden ping
__device__ __half g_hB  [(size_t)B_ * KH];        // hidden pong
__device__ __half g_out [(size_t)B_ * KD];        // final hidden (fp16)
__device__ __half g_WihP[(size_t)NP * KH];        // packed, rows 2976.. zero
__device__ __half g_WhhP[(size_t)NP * KH];
__device__ float  g_bihP[NP];                     // packed bias for GEMM1
__device__ float  g_bhh [3 * KH];                 // gate-major (d stride 1024)
__device__ float  g_psum[32 * KD];
__device__ float  g_psq [32 * KD];
__device__ float  g_weff[2 * D_];
__device__ float  g_wbn [2 * KD];                 // [991],[KD+991] stay zero
__device__ float  g_shift[KD];
__device__ float  g_bbn [2];
// ragged-batch bookkeeping (permuted row space, sorted by descending seq_len)
__device__ int    g_idx[B_];
__device__ int    g_sln[B_];
__device__ int    g_cnt[8];

// --------------------------- helpers ---------------------------------------
__device__ __forceinline__ uint32_t smem_u32(const void* p) {
    uint32_t a;
    asm("{ .reg .u64 t; cvta.to.shared.u64 t, %1; cvt.u32.u64 %0, t; }" : "=r"(a) : "l"(p));
    return a;
}
__device__ __forceinline__ void cp_async16(uint32_t dst, const void* src) {
    asm volatile("cp.async.cg.shared.global [%0], [%1], 16;" :: "r"(dst), "l"(src) : "memory");
}
#define CP_COMMIT() asm volatile("cp.async.commit_group;" ::: "memory")
#define CP_WAIT(n)  asm volatile("cp.async.wait_group %0;" :: "n"(n) : "memory")

__device__ __forceinline__ void ldm4(uint32_t* r, uint32_t addr) {
    asm volatile("ldmatrix.sync.aligned.m8n8.x4.shared.b16 {%0,%1,%2,%3}, [%4];"
                 : "=r"(r[0]), "=r"(r[1]), "=r"(r[2]), "=r"(r[3]) : "r"(addr));
}
__device__ __forceinline__ void mma_h(float* c, const uint32_t* a, const uint32_t* b) {
    asm volatile(
        "mma.sync.aligned.m16n8k16.row.col.f32.f16.f16.f32 "
        "{%0,%1,%2,%3}, {%4,%5,%6,%7}, {%8,%9}, {%0,%1,%2,%3};"
        : "+f"(c[0]), "+f"(c[1]), "+f"(c[2]), "+f"(c[3])
        : "r"(a[0]), "r"(a[1]), "r"(a[2]), "r"(a[3]), "r"(b[0]), "r"(b[1]));
}
__device__ __forceinline__ float fsigmoid(float x) {
    return 1.f / (1.f + __expf(-x));
}
__device__ __forceinline__ float ftanh(float x) {
    float e = __expf(2.f * x);
    return 1.f - __fdividef(2.f, e + 1.f);
}

__device__ __forceinline__ float2 block_reduce2(float a, float b) {
    __shared__ float wa[8], wb[8];
    __shared__ float ra, rb;
    int lane = threadIdx.x & 31, w = threadIdx.x >> 5;
#pragma unroll
    for (int o = 16; o; o >>= 1) {
        a += __shfl_down_sync(0xffffffffu, a, o);
        b += __shfl_down_sync(0xffffffffu, b, o);
    }
    if (!lane) { wa[w] = a; wb[w] = b; }
    __syncthreads();
    if (threadIdx.x < 8) { a = wa[threadIdx.x]; b = wb[threadIdx.x]; }
    else { a = 0.f; b = 0.f; }
    if (w == 0) {
#pragma unroll
        for (int o = 4; o; o >>= 1) {
            a += __shfl_down_sync(0xffffffffu, a, o);
            b += __shfl_down_sync(0xffffffffu, b, o);
        }
    }
    if (threadIdx.x == 0) { ra = a; rb = b; }
    __syncthreads();
    return make_float2(ra, rb);
}

// --------------------------- deterministic counting sort --------------------
__global__ void __launch_bounds__(1024)
sort_kernel(const int* __restrict__ seq_len) {
    __shared__ int cnts[1024][6];
    __shared__ int tot[6], base[6];
    const int tid = threadIdx.x;
    const int b0 = tid * 16;
    int lc[6] = {0, 0, 0, 0, 0, 0};
#pragma unroll
    for (int k = 0; k < 16; ++k) {
        int v = seq_len[b0 + k] - 1;
        lc[v]++;
    }
#pragma unroll
    for (int v = 0; v < 6; ++v) cnts[tid][v] = lc[v];
    __syncthreads();
    if (tid < 6) {
        int run = 0;
        for (int i = 0; i < 1024; ++i) {
            int c = cnts[i][tid];
            cnts[i][tid] = run;
            run += c;
        }
        tot[tid] = run;
    }
    __syncthreads();
    if (tid == 0) {
        int acc = 0;
        for (int v = 5; v >= 0; --v) { base[v] = acc; acc += tot[v]; }
        for (int s = 0; s < 6; ++s) {
            int c = 0;
            for (int v = s; v < 6; ++v) c += tot[v];
            g_cnt[s] = c;
        }
    }
    __syncthreads();
    int off[6];
#pragma unroll
    for (int v = 0; v < 6; ++v) off[v] = base[v] + cnts[tid][v];
#pragma unroll
    for (int k = 0; k < 16; ++k) {
        int b = b0 + k;
        int v = seq_len[b] - 1;
        int p = off[v]++;
        g_idx[p] = b;
        g_sln[p] = v + 1;
    }
}

// --------------------------- weight packing --------------------------------
// Packed row rp (0..3071): nt=rp/96, cc=rp%96, grp=cc>>3, gate=grp%3,
// d = nt*32 + (grp/3)*8 + (cc&7). rows >= 2976 or d >= 991 -> zero.
__global__ void pack_weights(const float* __restrict__ Wih, const float* __restrict__ Whh,
                             const float* __restrict__ bih, const float* __restrict__ bhh) {
    size_t i = (size_t)blockIdx.x * 256 + threadIdx.x;
    if (i >= (size_t)NP * KH) return;
    int rp = (int)(i / KH), c = (int)(i - (size_t)rp * KH);
    int nt = rp / 96, cc = rp - nt * 96;
    int grp = cc >> 3, gate = grp % 3;
    int d = nt * 32 + (grp / 3) * 8 + (cc & 7);
    bool valid = (rp < NPR) && (d < D_);
    float vi = 0.f, vh = 0.f;
    if (valid && c < D_) {
        size_t src = (size_t)(gate * D_ + d) * D_ + c;
        vi = Wih[src];
        vh = Whh[src];
    }
    g_WihP[i] = __float2half_rn(vi);
    g_WhhP[i] = __float2half_rn(vh);
    if (c == 0) {
        g_bihP[rp] = valid ? bih[gate * D_ + d] : 0.f;
        if (rp < NPR)
            g_bhh[gate * KH + d] = (d < D_) ? bhh[gate * D_ + d] : 0.f;
    }
}

// --------------------------- embed + layernorm (warp per row) --------------
__global__ void __launch_bounds__(256)
embed_ln(const int* __restrict__ ns, const int* __restrict__ fs,
         const int* __restrict__ nfs, const int* __restrict__ ms,
         const float* __restrict__ ntab, const float* __restrict__ ftab,
         const float* __restrict__ nftab, const float* __restrict__ btab,
         const float* __restrict__ lng, const float* __restrict__ lnb) {
    const int gid  = blockIdx.x * 8 + (threadIdx.x >> 5);   // row = s*B + p
    const int lane = threadIdx.x & 31;
    const int s = gid >> 14;
    const int p = gid & (B_ - 1);
    if (p >= g_cnt[s]) return;
    const int b = g_idx[p];
    const int q = b * S_ + s;
    const int ni = ns[q], fi = fs[q], nfi = nfs[q], mi = ms[q];
    const float* nrow  = ntab  + (size_t)ni  * 128;
    const float* frow  = ftab  + (size_t)fi  * 84;
    const float* nfrow = nftab + (size_t)nfi * 11;
    const float* brow  = btab  + (size_t)mi  * 768;

    float arr[31];
    float s1 = 0.f, s2 = 0.f;
#pragma unroll
    for (int k = 0; k < 31; ++k) {
        int d = lane + 32 * k;
        float v = 0.f;
        if (d < D_) {
            if (d < 128)      v = nrow[d];
            else if (d < 212) v = frow[d - 128];
            else if (d < 223) v = nfrow[d - 212];
            else              v = brow[d - 223];
        }
        arr[k] = v;
        s1 += v; s2 += v * v;
    }
#pragma unroll
    for (int o = 16; o; o >>= 1) {
        s1 += __shfl_xor_sync(0xffffffffu, s1, o);
        s2 += __shfl_xor_sync(0xffffffffu, s2, o);
    }
    const float mu  = s1 * (1.f / 991.f);
    const float var = fmaxf(s2 * (1.f / 991.f) - mu * mu, 0.f);
    const float rs  = rsqrtf(var + 1e-5f);
    __half* xr = g_x + (size_t)gid * KH;
#pragma unroll
    for (int k = 0; k < 32; ++k) {
        int d = lane + 32 * k;
        float v = 0.f;
        if (k < 31 && d < D_) v = (arr[k] - mu) * rs * lng[d] + lnb[d];
        xr[d] = __float2half_rn(v);
    }
}

// --------------------------- GEMM1: xg = x @ WihP^T + bihP -----------------
// 128x128 tile, 8 warps (4m x 2n), 2 CTA/SM, 3-stage, single sync/chunk.
// Tail chunk (cols 992..1023, all-zero) peeled: runs only ks=0,1.
__global__ void __launch_bounds__(256, 2)
gemm_h(const __half* __restrict__ A, const __half* __restrict__ Bw,
       __half* __restrict__ C, const float* __restrict__ bias) {
    const int mt = blockIdx.x / NT_, nt = blockIdx.x % NT_;
    {
        int mtl = mt & 127;
        int cnt = g_cnt[mt >> 7];
        if (mtl * TM >= cnt) return;
    }
    extern __shared__ char sm[];
    const uint32_t sb0 = smem_u32(sm);
    const int tid = threadIdx.x;

    const __half* Ab = A  + (size_t)mt * TM * KH;
    const __half* Bb = Bw + (size_t)nt * TN * KH;

    const int row0 = tid >> 3;
    const int cg   = tid & 7;
    const uint32_t rowOff0 = (uint32_t)row0 * KH + (uint32_t)cg * 8;
    const uint32_t dst0    = (uint32_t)row0 * 128 + (uint32_t)((cg ^ (row0 & 7)) << 4);

#define PREF(stagebase, k0_) do {                                            \
    _Pragma("unroll")                                                        \
    for (int t_ = 0; t_ < 4; ++t_) {                                         \
        cp_async16((stagebase) + dst0 + t_ * 4096,                           \
                   Ab + rowOff0 + (uint32_t)t_ * 32 * KH + (k0_));           \
        cp_async16((stagebase) + (TM * 128) + dst0 + t_ * 4096,              \
                   Bb + rowOff0 + (uint32_t)t_ * 32 * KH + (k0_));           \
    }                                                                        \
    CP_COMMIT();                                                             \
} while (0)

    const int lane = tid & 31, warp = tid >> 5;
    const int mw = (warp >> 1) * 32;
    const int nw = (warp & 1) * 64;
    const int g  = lane >> 2, q = lane & 3;

    uint32_t aRB[2];
#pragma unroll
    for (int i = 0; i < 2; ++i) aRB[i] = (uint32_t)(mw + i * 16 + (lane & 15)) * 128;
    const uint32_t aSw = (uint32_t)((mw + (lane & 15)) & 7);
    const uint32_t aPar = (uint32_t)(lane >> 4);
    uint32_t bRB[4], bSw[4];
#pragma unroll
    for (int jp = 0; jp < 4; ++jp) {
        uint32_t br = (uint32_t)(nw + jp * 16 + (lane & 7) + ((lane >> 4) << 3));
        bRB[jp] = br * 128;
        bSw[jp] = br & 7;
    }
    const uint32_t bPar = (uint32_t)((lane >> 3) & 1);

    float acc[2][8][4];
#pragma unroll
    for (int i = 0; i < 2; i++)
#pragma unroll
        for (int j = 0; j < 8; j++)
#pragma unroll
            for (int e = 0; e < 4; e++) acc[i][j][e] = 0.f;

    PREF(sb0, 0);
    PREF(sb0 + STB, KCH);

    // main loop: chunks 0..14, exact R15 body (full 4-ks, static unroll)
#pragma unroll 1
    for (int c = 0; c < NCHh - 1; ++c) {
        CP_WAIT(1);
        __syncthreads();
        if (c + 2 < NCHh) PREF(sb0 + ((c + 2) % 3) * STB, (uint32_t)(c + 2) * KCH);

        const uint32_t sA  = sb0 + (c % 3) * STB;
        const uint32_t sBq = sA + TM * 128;
        uint32_t a0[4], a1[4];
        {
            uint32_t kg = aPar;
            ldm4(a0, sA + aRB[0] + ((kg ^ aSw) << 4));
            ldm4(a1, sA + aRB[1] + ((kg ^ aSw) << 4));
        }
#pragma unroll
        for (int ks = 0; ks < 4; ++ks) {
            uint32_t an0[4], an1[4];
            if (ks < 3) {
                uint32_t kg = 2 * (ks + 1) + aPar;
                ldm4(an0, sA + aRB[0] + ((kg ^ aSw) << 4));
                ldm4(an1, sA + aRB[1] + ((kg ^ aSw) << 4));
            }
#pragma unroll
            for (int jp = 0; jp < 4; ++jp) {
                uint32_t bf[4];
                uint32_t kg = 2 * ks + bPar;
                ldm4(bf, sBq + bRB[jp] + ((kg ^ bSw[jp]) << 4));
                mma_h(acc[0][2 * jp],     a0, bf);
                mma_h(acc[0][2 * jp + 1], a0, bf + 2);
                mma_h(acc[1][2 * jp],     a1, bf);
                mma_h(acc[1][2 * jp + 1], a1, bf + 2);
            }
            if (ks < 3) {
#pragma unroll
                for (int e = 0; e < 4; ++e) { a0[e] = an0[e]; a1[e] = an1[e]; }
            }
        }
    }

    // peeled tail chunk 15: only ks=0,1 (k cols 992..1023 are all-zero)
    {
        CP_WAIT(0);
        __syncthreads();
        const uint32_t sA  = sb0 + ((NCHh - 1) % 3) * STB;
        const uint32_t sBq = sA + TM * 128;
        uint32_t a0[4], a1[4];
        {
            uint32_t kg = aPar;
            ldm4(a0, sA + aRB[0] + ((kg ^ aSw) << 4));
            ldm4(a1, sA + aRB[1] + ((kg ^ aSw) << 4));
        }
#pragma unroll
        for (int ks = 0; ks < 2; ++ks) {
            uint32_t an0[4], an1[4];
            if (ks < 1) {
                uint32_t kg = 2 + aPar;
                ldm4(an0, sA + aRB[0] + ((kg ^ aSw) << 4));
                ldm4(an1, sA + aRB[1] + ((kg ^ aSw) << 4));
            }
#pragma unroll
            for (int jp = 0; jp < 4; ++jp) {
                uint32_t bf[4];
                uint32_t kg = 2 * ks + bPar;
                ldm4(bf, sBq + bRB[jp] + ((kg ^ bSw[jp]) << 4));
                mma_h(acc[0][2 * jp],     a0, bf);
                mma_h(acc[0][2 * jp + 1], a0, bf + 2);
                mma_h(acc[1][2 * jp],     a1, bf);
                mma_h(acc[1][2 * jp + 1], a1, bf + 2);
            }
            if (ks < 1) {
#pragma unroll
                for (int e = 0; e < 4; ++e) { a0[e] = an0[e]; a1[e] = an1[e]; }
            }
        }
    }
#undef PREF

    const long m0 = (long)mt * TM;
    const int  n0 = nt * TN;
#pragma unroll
    for (int i = 0; i < 2; ++i) {
        const long r0 = m0 + mw + i * 16 + g;
#pragma unroll
        for (int j = 0; j < 8; ++j) {
            const int colg = n0 + nw + j * 8 + 2 * q;
            const float2 bb = *(const float2*)(bias + colg);
            *(__half2*)(C + r0 * NP + colg) =
                __floats2half2_rn(acc[i][j][0] + bb.x, acc[i][j][1] + bb.y);
            *(__half2*)(C + (r0 + 8) * NP + colg) =
                __floats2half2_rn(acc[i][j][2] + bb.x, acc[i][j][3] + bb.y);
        }
    }
}

// --------------------------- recurrent GEMM + fused GRU --------------------
// gh = h_in @ WhhP^T; epilogue applies GRU gates, writes h_out (ping-pong).
// Tile 128x96, 8 warps (4m x 2n), warp tile 32x48. Tail chunk peeled (2 ks).
__global__ void __launch_bounds__(256, 2)
gemm_rec(const __half* __restrict__ Hin, __half* __restrict__ Hout, int step) {
    const int mt = blockIdx.x / NTR, nt = blockIdx.x % NTR;
    if (mt * TM >= g_cnt[step]) return;
    extern __shared__ char sm[];
    const uint32_t sb0 = smem_u32(sm);
    const int tid = threadIdx.x;

    const __half* Ab = Hin    + (size_t)mt * TM * KH;
    const __half* Bb = g_WhhP + (size_t)nt * TNR * KH;

    const int row0 = tid >> 3;
    const int cg   = tid & 7;
    const uint32_t rowOff0 = (uint32_t)row0 * KH + (uint32_t)cg * 8;
    const uint32_t dst0    = (uint32_t)row0 * 128 + (uint32_t)((cg ^ (row0 & 7)) << 4);

#define PREFR(stagebase, k0_) do {                                           \
    _Pragma("unroll")                                                        \
    for (int t_ = 0; t_ < 4; ++t_)                                           \
        cp_async16((stagebase) + dst0 + t_ * 4096,                           \
                   Ab + rowOff0 + (uint32_t)t_ * 32 * KH + (k0_));           \
    _Pragma("unroll")                                                        \
    for (int t_ = 0; t_ < 3; ++t_)                                           \
        cp_async16((stagebase) + (TM * 128) + dst0 + t_ * 4096,              \
                   Bb + rowOff0 + (uint32_t)t_ * 32 * KH + (k0_));           \
    CP_COMMIT();                                                             \
} while (0)

    const int lane = tid & 31, warp = tid >> 5;
    const int mw = (warp >> 1) * 32;    // 4 m-warps
    const int nw = (warp & 1) * 48;     // 2 n-warps
    const int g  = lane >> 2, q = lane & 3;

    uint32_t aRB[2];
#pragma unroll
    for (int i = 0; i < 2; ++i) aRB[i] = (uint32_t)(mw + i * 16 + (lane & 15)) * 128;
    const uint32_t aSw = (uint32_t)((mw + (lane & 15)) & 7);
    const uint32_t aPar = (uint32_t)(lane >> 4);
    uint32_t bRB[3], bSw[3];
#pragma unroll
    for (int jp = 0; jp < 3; ++jp) {
        uint32_t br = (uint32_t)(nw + jp * 16 + (lane & 7) + ((lane >> 4) << 3));
        bRB[jp] = br * 128;
        bSw[jp] = br & 7;
    }
    const uint32_t bPar = (uint32_t)((lane >> 3) & 1);

    float acc[2][6][4];
#pragma unroll
    for (int i = 0; i < 2; i++)
#pragma unroll
        for (int j = 0; j < 6; j++)
#pragma unroll
            for (int e = 0; e < 4; e++) acc[i][j][e] = 0.f;

    PREFR(sb0, 0);
    PREFR(sb0 + STBR, KCH);

    // main loop: chunks 0..14 (full 4-ks body)
#pragma unroll 1
    for (int c = 0; c < NCHh - 1; ++c) {
        CP_WAIT(1);
        __syncthreads();
        if (c + 2 < NCHh) PREFR(sb0 + ((c + 2) % 3) * STBR, (uint32_t)(c + 2) * KCH);

        const uint32_t sA  = sb0 + (c % 3) * STBR;
        const uint32_t sBq = sA + TM * 128;
        uint32_t a0[4], a1[4];
        {
            uint32_t kg = aPar;
            ldm4(a0, sA + aRB[0] + ((kg ^ aSw) << 4));
            ldm4(a1, sA + aRB[1] + ((kg ^ aSw) << 4));
        }
#pragma unroll
        for (int ks = 0; ks < 4; ++ks) {
            uint32_t an0[4], an1[4];
            if (ks < 3) {
                uint32_t kg = 2 * (ks + 1) + aPar;
                ldm4(an0, sA + aRB[0] + ((kg ^ aSw) << 4));
                ldm4(an1, sA + aRB[1] + ((kg ^ aSw) << 4));
            }
#pragma unroll
            for (int jp = 0; jp < 3; ++jp) {
                uint32_t bf[4];
                uint32_t kg = 2 * ks + bPar;
                ldm4(bf, sBq + bRB[jp] + ((kg ^ bSw[jp]) << 4));
                mma_h(acc[0][2 * jp],     a0, bf);
                mma_h(acc[0][2 * jp + 1], a0, bf + 2);
                mma_h(acc[1][2 * jp],     a1, bf);
                mma_h(acc[1][2 * jp + 1], a1, bf + 2);
            }
            if (ks < 3) {
#pragma unroll
                for (int e = 0; e < 4; ++e) { a0[e] = an0[e]; a1[e] = an1[e]; }
            }
        }
    }

    // peeled tail chunk 15: only ks=0,1
    {
        CP_WAIT(0);
        __syncthreads();
        const uint32_t sA  = sb0 + ((NCHh - 1) % 3) * STBR;
        const uint32_t sBq = sA + TM * 128;
        uint32_t a0[4], a1[4];
        {
            uint32_t kg = aPar;
            ldm4(a0, sA + aRB[0] + ((kg ^ aSw) << 4));
            ldm4(a1, sA + aRB[1] + ((kg ^ aSw) << 4));
        }
#pragma unroll
        for (int ks = 0; ks < 2; ++ks) {
            uint32_t an0[4], an1[4];
            if (ks < 1) {
                uint32_t kg = 2 + aPar;
                ldm4(an0, sA + aRB[0] + ((kg ^ aSw) << 4));
                ldm4(an1, sA + aRB[1] + ((kg ^ aSw) << 4));
            }
#pragma unroll
            for (int jp = 0; jp < 3; ++jp) {
                uint32_t bf[4];
                uint32_t kg = 2 * ks + bPar;
                ldm4(bf, sBq + bRB[jp] + ((kg ^ bSw[jp]) << 4));
                mma_h(acc[0][2 * jp],     a0, bf);
                mma_h(acc[0][2 * jp + 1], a0, bf + 2);
                mma_h(acc[1][2 * jp],     a1, bf);
                mma_h(acc[1][2 * jp + 1], a1, bf + 2);
            }
            if (ks < 1) {
#pragma unroll
                for (int e = 0; e < 4; ++e) { a0[e] = an0[e]; a1[e] = an1[e]; }
            }
        }
    }
#undef PREFR

    // fused GRU epilogue. acc[i][j]: gate = j%3, d-block b = j/3.
    const long m0 = (long)mt * TM;
    const int  w1 = warp & 1;
    const __half* xgbase = g_xg + (size_t)step * B_ * NP;
#pragma unroll
    for (int i = 0; i < 2; ++i) {
        const long R = m0 + mw + i * 16 + g;
        const int sl0 = g_sln[R], sl1 = g_sln[R + 8];
#pragma unroll
        for (int b = 0; b < 2; ++b) {
            const int D   = nt * 32 + (w1 * 2 + b) * 8 + 2 * q;
            const int rpb = nt * 96 + (w1 * 2 + b) * 24 + 2 * q;
            const float2 br_ = *(const float2*)(g_bhh + D);
            const float2 bz_ = *(const float2*)(g_bhh + KH + D);
            const float2 bn_ = *(const float2*)(g_bhh + 2 * KH + D);
#pragma unroll
            for (int half_ = 0; half_ < 2; ++half_) {
                const long row = R + half_ * 8;
                const int  sl  = half_ ? sl1 : sl0;
                const int  eo  = half_ * 2;
                const __half2* xgr = (const __half2*)(xgbase + row * NP);
                float2 xr = __half22float2(xgr[(rpb >> 1)]);
                float2 xz = __half22float2(xgr[(rpb >> 1) + 4]);
                float2 xn = __half22float2(xgr[(rpb >> 1) + 8]);
                float2 hp = __half22float2(*(const __half2*)(Hin + row * KH + D));
                float r0 = fsigmoid(xr.x + acc[i][3 * b + 0][eo]     + br_.x);
                float r1 = fsigmoid(xr.y + acc[i][3 * b + 0][eo + 1] + br_.y);
                float z0 = fsigmoid(xz.x + acc[i][3 * b + 1][eo]     + bz_.x);
                float z1 = fsigmoid(xz.y + acc[i][3 * b + 1][eo + 1] + bz_.y);
                float n0 = ftanh(xn.x + r0 * (acc[i][3 * b + 2][eo]     + bn_.x));
                float n1 = ftanh(xn.y + r1 * (acc[i][3 * b + 2][eo + 1] + bn_.y));
                float h0 = (1.f - z0) * n0 + z0 * hp.x;
                float h1 = (1.f - z1) * n1 + z1 * hp.y;
                __half2 hh = __floats2half2_rn(h0, h1);
                *(__half2*)(Hout + row * KH + D) = hh;
                if (sl - 1 == step)
                    *(__half2*)(g_out + row * KD + D) = hh;
            }
        }
    }
}

// --------------------------- GRU t=0 (h0=0, gh=b_hh; packed xg) ------------
__global__ void __launch_bounds__(1024)
gru0() {
    unsigned i = blockIdx.x * 1024u + threadIdx.x;
    if (i >= (unsigned)(B_ * 496)) return;
    int p = i / 496;
    int j = i - p * 496;
    const int d  = 2 * j;                 // 0..990
    const int rp = (d >> 5) * 96 + ((d & 31) >> 3) * 24 + (d & 7);
    const __half2* xg = (const __half2*)(g_xg + (size_t)p * NP);
    float2 xr = __half22float2(xg[(rp >> 1)]);
    float2 xz = __half22float2(xg[(rp >> 1) + 4]);
    float2 xn = __half22float2(xg[(rp >> 1) + 8]);
    float2 hr = *(const float2*)(g_bhh + d);
    float2 hz = *(const float2*)(g_bhh + KH + d);
    float2 hn = *(const float2*)(g_bhh + 2 * KH + d);
    float r0 = fsigmoid(xr.x + hr.x);
    float r1 = fsigmoid(xr.y + hr.y);
    float z0 = fsigmoid(xz.x + hz.x);
    float z1 = fsigmoid(xz.y + hz.y);
    float n0 = ftanh(xn.x + r0 * hn.x);
    float n1 = ftanh(xn.y + r1 * hn.y);
    float h0 = (1.f - z0) * n0;
    float h1 = (1.f - z1) * n1;
    __half2 hh = __floats2half2_rn(h0, h1);
    *(__half2*)(g_hA + (size_t)p * KH + d) = hh;
    if (g_sln[p] == 1)
        *(__half2*)(g_out + (size_t)p * KD + d) = hh;
}

// --------------------------- batchnorm + folded head -----------------------
// g_out is half; process half2 columns (496 per row).
__global__ void bn_partial() {
    __shared__ float ssx[8][33], sqx[8][33], ssy[8][33], sqy[8][33];
    int col2 = blockIdx.x * 32 + threadIdx.x;   // 0..495 (+pad)
    int ty = threadIdx.y;
    float sx = 0.f, qx = 0.f, sy = 0.f, qy = 0.f;
    if (col2 < 496) {
        for (int r = blockIdx.y * 8 + ty; r < B_; r += 256) {
            float2 v = __half22float2(((const __half2*)(g_out + (size_t)r * KD))[col2]);
            sx += v.x; qx += v.x * v.x;
            sy += v.y; qy += v.y * v.y;
        }
    }
    ssx[ty][threadIdx.x] = sx; sqx[ty][threadIdx.x] = qx;
    ssy[ty][threadIdx.x] = sy; sqy[ty][threadIdx.x] = qy;
    __syncthreads();
    if (ty == 0 && col2 < 496) {
        float Sx = 0.f, Qx = 0.f, Sy = 0.f, Qy = 0.f;
#pragma unroll
        for (int k = 0; k < 8; k++) {
            Sx += ssx[k][threadIdx.x]; Qx += sqx[k][threadIdx.x];
            Sy += ssy[k][threadIdx.x]; Qy += sqy[k][threadIdx.x];
        }
        g_psum[blockIdx.y * KD + 2 * col2]     = Sx;
        g_psq [blockIdx.y * KD + 2 * col2]     = Qx;
        g_psum[blockIdx.y * KD + 2 * col2 + 1] = Sy;
        g_psq [blockIdx.y * KD + 2 * col2 + 1] = Qy;
    }
}

__global__ void weff_kernel(const float* __restrict__ W2, const float* __restrict__ W1) {
    int gw   = blockIdx.x * 8 + (threadIdx.x >> 5);
    int lane = threadIdx.x & 31;
    if (gw >= 2 * D_) return;
    int o = gw / D_, d = gw - o * D_;
    float acc = 0.f;
    for (int j = lane; j < 2 * D_; j += 32)
        acc += W2[o * (2 * D_) + j] * W1[(size_t)j * D_ + d];
#pragma unroll
    for (int off = 16; off; off >>= 1) acc += __shfl_down_sync(0xffffffffu, acc, off);
    if (lane == 0) g_weff[gw] = acc;
}

__global__ void bn_finalize(const float* __restrict__ bn_g, const float* __restrict__ bn_b) {
    int d = blockIdx.x * 256 + threadIdx.x;
    if (d >= D_) return;
    float s = 0.f, q = 0.f;
#pragma unroll
    for (int p = 0; p < 32; p++) { s += g_psum[p * KD + d]; q += g_psq[p * KD + d]; }
    float mu  = s * (1.f / 16384.f);
    float var = fmaxf(q * (1.f / 16384.f) - mu * mu, 0.f);
    float sc  = bn_g[d] * rsqrtf(var + 1e-4f);
    g_shift[d]    = bn_b[d] - mu * sc;
    g_wbn[d]      = g_weff[d]      * sc;
    g_wbn[KD + d] = g_weff[D_ + d] * sc;
}

__global__ void bbn_kernel(const float* __restrict__ W2, const float* __restrict__ b1,
                           const float* __restrict__ b2) {
    int o = blockIdx.x;
    float acc = 0.f;
    for (int j = threadIdx.x; j < 2 * D_; j += 256) acc += W2[o * (2 * D_) + j] * b1[j];
    for (int d = threadIdx.x; d < D_; d += 256)     acc += g_weff[o * D_ + d] * g_shift[d];
    float2 t = block_reduce2(acc, 0.f);
    if (threadIdx.x == 0) g_bbn[o] = t.x + b2[o];
}

__global__ void logits_kernel(float* __restrict__ out) {
    int gw   = (blockIdx.x * 256 + threadIdx.x) >> 5;
    int lane = threadIdx.x & 31;
    if (gw >= B_) return;
    const __half2* row = (const __half2*)(g_out + (size_t)gw * KD);
    float a0 = 0.f, a1 = 0.f;
    for (int d2 = lane; d2 < 496; d2 += 32) {      // col 991 pad: wbn[991]=0
        float2 v = __half22float2(row[d2]);
        const float2 w0 = *(const float2*)(g_wbn + 2 * d2);
        const float2 w1 = *(const float2*)(g_wbn + KD + 2 * d2);
        a0 += v.x * w0.x + v.y * w0.y;
        a1 += v.x * w1.x + v.y * w1.y;
    }
#pragma unroll
    for (int o = 16; o; o >>= 1) {
        a0 += __shfl_down_sync(0xffffffffu, a0, o);
        a1 += __shfl_down_sync(0xffffffffu, a1, o);
    }
    if (lane == 0) {
        int b = g_idx[gw];
        out[2 * b]     = a0 + g_bbn[0];
        out[2 * b + 1] = a1 + g_bbn[1];
    }
}

// --------------------------- launch -----------------------------------------
extern "C" void kernel_launch(void* const* d_in, const int* in_sizes, int n_in,
                              void* d_out, int out_size) {
    const int*   node_seq   = (const int*)d_in[0];
    const int*   fin_seq    = (const int*)d_in[1];
    const int*   nfin_seq   = (const int*)d_in[2];
    const int*   mda_seq    = (const int*)d_in[3];
    const int*   seq_len    = (const int*)d_in[4];
    const float* node_table = (const float*)d_in[5];
    const float* fin_table  = (const float*)d_in[6];
    const float* nfin_table = (const float*)d_in[7];
    const float* bert_table = (const float*)d_in[8];
    const float* ln_g = (const float*)d_in[9];
    const float* ln_b = (const float*)d_in[10];
    const float* W_ih = (const float*)d_in[11];
    const float* W_hh = (const float*)d_in[12];
    const float* b_ih = (const float*)d_in[13];
    const float* b_hh = (const float*)d_in[14];
    const float* bn_g = (const float*)d_in[15];
    const float* bn_b = (const float*)d_in[16];
    const float* W1   = (const float*)d_in[17];
    const float* b1   = (const float*)d_in[18];
    const float* W2   = (const float*)d_in[19];
    const float* b2   = (const float*)d_in[20];

    __half *px, *pxg, *pWihP, *phA, *phB;
    float *pbihP;
    cudaGetSymbolAddress((void**)&px,    g_x);
    cudaGetSymbolAddress((void**)&pxg,   g_xg);
    cudaGetSymbolAddress((void**)&pWihP, g_WihP);
    cudaGetSymbolAddress((void**)&pbihP, g_bihP);
    cudaGetSymbolAddress((void**)&phA,   g_hA);
    cudaGetSymbolAddress((void**)&phB,   g_hB);

    cudaFuncSetAttribute(gemm_h,   cudaFuncAttributeMaxDynamicSharedMemorySize, SMEMB);
    cudaFuncSetAttribute(gemm_rec, cudaFuncAttributeMaxDynamicSharedMemorySize, SMEMR);

    sort_kernel<<<1, 1024>>>(seq_len);
    pack_weights<<<(NP * KH + 255) / 256, 256>>>(W_ih, W_hh, b_ih, b_hh);
    embed_ln<<<B_ * S_ / 8, 256>>>(node_seq, fin_seq, nfin_seq, mda_seq,
                                   node_table, fin_table, nfin_table, bert_table,
                                   ln_g, ln_b);

    // GEMM1: xg = x @ WihP^T + bihP  (ragged: per-s active prefix)
    gemm_h<<<(B_ * S_ / TM) * NT_, 256, SMEMB>>>(px, pWihP, pxg, pbihP);

    // GRU t=0 (h0=0 => gh = b_hh) -> writes g_hA
    gru0<<<(B_ * 496 + 1023) / 1024, 1024>>>();

    // steps 1..5: recurrent GEMM with fused GRU epilogue (ping-pong h)
    __half* bufs[2] = {phA, phB};
    for (int t = 1; t < S_; ++t) {
        __half* hin  = bufs[(t + 1) & 1];
        __half* hout = bufs[t & 1];
        gemm_rec<<<(B_ / TM) * NTR, 256, SMEMR>>>(hin, hout, t);
    }

    // head constant-folding (independent; late so ncu slot catches GEMMs)
    weff_kernel<<<(2 * D_ + 7) / 8, 256>>>(W2, W1);

    // batchnorm stats + folded head
    bn_partial<<<dim3(16, 32), dim3(32, 8)>>>();
    bn_finalize<<<(D_ + 255) / 256, 256>>>(bn_g, bn_b);
    bbn_kernel<<<2, 256>>>(W2, b1, b2);
    logits_kernel<<<(B_ * 32 + 255) / 256, 256>>>((float*)d_out);
}